// round 13
// baseline (speedup 1.0000x reference)
#include <cuda_runtime.h>
#include <cuda_fp16.h>
#include <math.h>

#define T_TOK 2048
#define DIM   2048
#define NEXP  8
#define FDIM  1408
#define D2    (DIM / 2)     // 1024
#define F2    (FDIM / 2)    // 704

// ---- device scratch (no allocations allowed) ----
__device__ int     g_cnt[NEXP];
__device__ int     g_tok[NEXP][T_TOK];                      // tok | (which<<12)
__device__ float   g_wt [NEXP][T_TOK];
__device__ __half  g_xh [(size_t)T_TOK * DIM];              // x as half
__device__ __half2 g_wgi[(size_t)NEXP * D2 * FDIM];         // wg, k-pair interleaved
__device__ __half2 g_wui[(size_t)NEXP * D2 * FDIM];         // wu, k-pair interleaved
__device__ __half2 g_wdi[(size_t)NEXP * F2 * DIM];          // wd, k-pair interleaved
__device__ __half  g_h  [(size_t)NEXP * T_TOK * FDIM];      // SiLU(xWg)*(xWu)*w (half)
__device__ float   g_c  [2][(size_t)T_TOK * DIM];           // per-(token,which) down contribs

// ---------------------------------------------------------------------------
__device__ __forceinline__ void mma_f16(float* c, const unsigned* a,
                                        unsigned b0, unsigned b1) {
    asm volatile(
        "mma.sync.aligned.m16n8k16.row.col.f32.f16.f16.f32 "
        "{%0,%1,%2,%3}, {%4,%5,%6,%7}, {%8,%9}, {%0,%1,%2,%3};\n"
        : "+f"(c[0]), "+f"(c[1]), "+f"(c[2]), "+f"(c[3])
        : "r"(a[0]), "r"(a[1]), "r"(a[2]), "r"(a[3]), "r"(b0), "r"(b1));
}
__device__ __forceinline__ void ldsm4(unsigned* a, unsigned addr) {
    asm volatile("ldmatrix.sync.aligned.m8n8.x4.shared.b16 {%0,%1,%2,%3}, [%4];"
        : "=r"(a[0]), "=r"(a[1]), "=r"(a[2]), "=r"(a[3]) : "r"(addr));
}
__device__ __forceinline__ void cp16(void* sdst, const void* gsrc) {
    unsigned s = (unsigned)__cvta_generic_to_shared(sdst);
    asm volatile("cp.async.cg.shared.global [%0], [%1], 16;\n" :: "r"(s), "l"(gsrc));
}
__device__ __forceinline__ void cp_commit() { asm volatile("cp.async.commit_group;\n"); }
template <int N>
__device__ __forceinline__ void cp_wait() { asm volatile("cp.async.wait_group %0;\n" :: "n"(N)); }

// ---------------------------------------------------------------------------
// conversion kernels (run each replay; deterministic)
// ---------------------------------------------------------------------------
// wg/wu: [E][D][F] fp32 -> [E][D/2][F] half2 (pair over D); also resets g_cnt
__global__ void conv_gu(const float* __restrict__ wg, const float* __restrict__ wu) {
    if (blockIdx.x == 0 && threadIdx.x < NEXP) g_cnt[threadIdx.x] = 0;
    int id = blockIdx.x * blockDim.x + threadIdx.x;
    int e   = id / (D2 * (FDIM / 4));
    int rem = id % (D2 * (FDIM / 4));
    int d2  = rem / (FDIM / 4);
    int f   = (rem % (FDIM / 4)) * 4;
    size_t ibase = ((size_t)e * DIM + 2 * d2) * FDIM + f;
    size_t obase = ((size_t)e * D2 + d2) * FDIM + f;
    {
        float4 a0 = *(const float4*)(wg + ibase);
        float4 a1 = *(const float4*)(wg + ibase + FDIM);
        __half2 h[4];
        h[0] = __floats2half2_rn(a0.x, a1.x);
        h[1] = __floats2half2_rn(a0.y, a1.y);
        h[2] = __floats2half2_rn(a0.z, a1.z);
        h[3] = __floats2half2_rn(a0.w, a1.w);
        *(uint4*)(g_wgi + obase) = *(uint4*)h;
    }
    {
        float4 a0 = *(const float4*)(wu + ibase);
        float4 a1 = *(const float4*)(wu + ibase + FDIM);
        __half2 h[4];
        h[0] = __floats2half2_rn(a0.x, a1.x);
        h[1] = __floats2half2_rn(a0.y, a1.y);
        h[2] = __floats2half2_rn(a0.z, a1.z);
        h[3] = __floats2half2_rn(a0.w, a1.w);
        *(uint4*)(g_wui + obase) = *(uint4*)h;
    }
}

// wd: [E][F][D] fp32 -> [E][F/2][D] half2 (pair over F)
__global__ void conv_wd(const float* __restrict__ wd) {
    int id = blockIdx.x * blockDim.x + threadIdx.x;
    int e   = id / (F2 * (DIM / 4));
    int rem = id % (F2 * (DIM / 4));
    int f2  = rem / (DIM / 4);
    int d   = (rem % (DIM / 4)) * 4;
    size_t ibase = ((size_t)e * FDIM + 2 * f2) * DIM + d;
    float4 a0 = *(const float4*)(wd + ibase);
    float4 a1 = *(const float4*)(wd + ibase + DIM);
    __half2 h[4];
    h[0] = __floats2half2_rn(a0.x, a1.x);
    h[1] = __floats2half2_rn(a0.y, a1.y);
    h[2] = __floats2half2_rn(a0.z, a1.z);
    h[3] = __floats2half2_rn(a0.w, a1.w);
    *(uint4*)(g_wdi + ((size_t)e * F2 + f2) * DIM + d) = *(uint4*)h;
}

// ---------------------------------------------------------------------------
// router: logits -> softmax -> top2 -> renorm -> scatter to expert lists.
// Also converts this token's x row to half (fuses old conv_x).
// One block (128 threads) per token; float4 loads.
// ---------------------------------------------------------------------------
__global__ void router_kernel(const float* __restrict__ x,
                              const float* __restrict__ gw) {
    int t   = blockIdx.x;
    int tid = threadIdx.x;

    float p[NEXP];
#pragma unroll
    for (int e = 0; e < NEXP; e++) p[e] = 0.0f;

    const float* xr = x + (size_t)t * DIM;
    __half* xh = g_xh + (size_t)t * DIM;
#pragma unroll
    for (int it = 0; it < DIM / 512; it++) {
        int d = (it * 128 + tid) * 4;
        float4 xv = *(const float4*)(xr + d);
        // fused conversion to half
        __half2 hv[2];
        hv[0] = __floats2half2_rn(xv.x, xv.y);
        hv[1] = __floats2half2_rn(xv.z, xv.w);
        *(uint2*)(xh + d) = *(uint2*)hv;
#pragma unroll
        for (int e = 0; e < NEXP; e++) {
            float4 gv = *(const float4*)(gw + e * DIM + d);
            p[e] += xv.x * gv.x + xv.y * gv.y + xv.z * gv.z + xv.w * gv.w;
        }
    }

    __shared__ float sm[NEXP][128];
#pragma unroll
    for (int e = 0; e < NEXP; e++) sm[e][tid] = p[e];
    __syncthreads();

    for (int s = 64; s > 0; s >>= 1) {
        if (tid < s) {
#pragma unroll
            for (int e = 0; e < NEXP; e++) sm[e][tid] += sm[e][tid + s];
        }
        __syncthreads();
    }

    if (tid == 0) {
        float lg[NEXP];
        float mx = -1e30f;
#pragma unroll
        for (int e = 0; e < NEXP; e++) { lg[e] = sm[e][0]; mx = fmaxf(mx, lg[e]); }
        float pr[NEXP];
#pragma unroll
        for (int e = 0; e < NEXP; e++) pr[e] = expf(lg[e] - mx);
        int e0 = 0;
#pragma unroll
        for (int e = 1; e < NEXP; e++) if (pr[e] > pr[e0]) e0 = e;
        int e1 = (e0 == 0) ? 1 : 0;
#pragma unroll
        for (int e = 0; e < NEXP; e++)
            if (e != e0 && pr[e] > pr[e1]) e1 = e;
        float denom = pr[e0] + pr[e1];
        float w0 = pr[e0] / denom;
        float w1 = pr[e1] / denom;
        int p0 = atomicAdd(&g_cnt[e0], 1);
        g_tok[e0][p0] = t;          g_wt[e0][p0] = w0;   // which = 0
        int p1 = atomicAdd(&g_cnt[e1], 1);
        g_tok[e1][p1] = t | 4096;   g_wt[e1][p1] = w1;   // which = 1
    }
}

// ---------------------------------------------------------------------------
#define AW 40    // A row: 40 halves (80B) -> LDSM conflict-free
#define BW 136   // B row: 136 half2 -> stride mod 32 == 8, conflict-free

// ---------------------------------------------------------------------------
// gate+up GEMM: 128 x 128(per matrix) x 32, fp16, 4-stage cp.async, ldmatrix A
// 512 threads, 16 warps (2M x 8N), warp tile 64x16 per matrix; dynamic smem
// ---------------------------------------------------------------------------
#define GU_S 4
#define GU_A_BYTES (128 * AW * 2)        // 10240
#define GU_B_BYTES (16 * BW * 4)         // 8704
#define GU_SMEM (GU_S * (GU_A_BYTES + 2 * GU_B_BYTES))   // 110592

__global__ void __launch_bounds__(512, 1)
gateup_mma() {
    extern __shared__ char dsm[];
    __half*  As = (__half*)dsm;                                       // [GU_S][128*AW]
    __half2* Bg = (__half2*)(dsm + GU_S * GU_A_BYTES);                // [GU_S][16*BW]
    __half2* Bu = (__half2*)(dsm + GU_S * (GU_A_BYTES + GU_B_BYTES)); // [GU_S][16*BW]

    __shared__ int   stok[128];
    __shared__ float swt[128];

    int e   = blockIdx.z;
    int cnt = g_cnt[e];
    int m0  = blockIdx.y * 128;
    if (m0 >= cnt) return;
    int n0  = blockIdx.x * 128;

    int tid = threadIdx.x;
    if (tid < 128) {
        int m = m0 + tid;
        int v = (m < cnt) ? g_tok[e][m] : 0;
        stok[tid] = v & 4095;
        swt[tid]  = (m < cnt) ? g_wt[e][m] : 0.0f;
    }
    __syncthreads();

    const __half2* wgE = g_wgi + (size_t)e * D2 * FDIM;
    const __half2* wuE = g_wui + (size_t)e * D2 * FDIM;

    int wid  = tid >> 5, lane = tid & 31;
    int gid  = lane >> 2, tig = lane & 3;
    int warpM = wid & 1, warpN = wid >> 1;       // 2 x 8 warps
    int wm = warpM * 64, wn = warpN * 16;

    int arow = tid >> 2, acol = (tid & 3) * 8;           // A: 128 rows x 4 chunks
    int bkr  = tid >> 5, bn = (tid & 31) * 4;            // B: 16 rows x 32 chunks

    int lrow = wm + (lane & 15), lchunk = (lane >> 4) * 8;

    const __half* xr0 = g_xh + (size_t)stok[arow] * DIM + acol;

    float cg[4][2][4] = {}, cu[4][2][4] = {};

    const int KT = DIM / 32;     // 64

    // prologue
#pragma unroll
    for (int s = 0; s < GU_S - 1; s++) {
        int kb = s * 32, kb2 = s * 16;
        cp16(&As[s * 128 * AW + arow * AW + acol], xr0 + kb);
        cp16(&Bg[s * 16 * BW + bkr * BW + bn], wgE + (size_t)(kb2 + bkr) * FDIM + n0 + bn);
        cp16(&Bu[s * 16 * BW + bkr * BW + bn], wuE + (size_t)(kb2 + bkr) * FDIM + n0 + bn);
        cp_commit();
    }

    for (int kt = 0; kt < KT; kt++) {
        cp_wait<GU_S - 2>();
        __syncthreads();

        int ln = kt + GU_S - 1;
        if (ln < KT) {
            int s = ln % GU_S;
            int kb = ln * 32, kb2 = ln * 16;
            cp16(&As[s * 128 * AW + arow * AW + acol], xr0 + kb);
            cp16(&Bg[s * 16 * BW + bkr * BW + bn], wgE + (size_t)(kb2 + bkr) * FDIM + n0 + bn);
            cp16(&Bu[s * 16 * BW + bkr * BW + bn], wuE + (size_t)(kb2 + bkr) * FDIM + n0 + bn);
        }
        cp_commit();

        int cs = kt % GU_S;
        const __half*  Ac = As + cs * 128 * AW;
        const __half2* Gc = Bg + cs * 16 * BW;
        const __half2* Uc = Bu + cs * 16 * BW;
#pragma unroll
        for (int ks = 0; ks < 2; ks++) {
            unsigned abase = (unsigned)__cvta_generic_to_shared(
                &Ac[lrow * AW + ks * 16 + lchunk]);
            unsigned a[4][4];
#pragma unroll
            for (int mi = 0; mi < 4; mi++)
                ldsm4(a[mi], abase + (unsigned)(mi * 16 * AW * 2));
#pragma unroll
            for (int ni = 0; ni < 2; ni++) {
                int nc = wn + ni * 8 + gid;
                unsigned bg0 = *(const unsigned*)&Gc[(ks * 8 + tig    ) * BW + nc];
                unsigned bg1 = *(const unsigned*)&Gc[(ks * 8 + tig + 4) * BW + nc];
                unsigned bu0 = *(const unsigned*)&Uc[(ks * 8 + tig    ) * BW + nc];
                unsigned bu1 = *(const unsigned*)&Uc[(ks * 8 + tig + 4) * BW + nc];
#pragma unroll
                for (int mi = 0; mi < 4; mi++) {
                    mma_f16(cg[mi][ni], a[mi], bg0, bg1);
                    mma_f16(cu[mi][ni], a[mi], bu0, bu1);
                }
            }
        }
    }

    // epilogue: SiLU(g)*u*w -> g_h (half)
#pragma unroll
    for (int mi = 0; mi < 4; mi++) {
#pragma unroll
        for (int half = 0; half < 2; half++) {
            int lm = wm + mi * 16 + gid + half * 8;
            int m  = m0 + lm;
            if (m >= cnt) continue;
            float w = swt[lm];
            __half* hrow = g_h + ((size_t)e * T_TOK + m) * FDIM + n0;
#pragma unroll
            for (int ni = 0; ni < 2; ni++) {
                int col = wn + ni * 8 + 2 * tig;
                float g0 = cg[mi][ni][half * 2 + 0], g1 = cg[mi][ni][half * 2 + 1];
                float u0 = cu[mi][ni][half * 2 + 0], u1 = cu[mi][ni][half * 2 + 1];
                float h0 = (g0 / (1.0f + __expf(-g0))) * u0 * w;
                float h1 = (g1 / (1.0f + __expf(-g1))) * u1 * w;
                *(__half2*)(hrow + col) = __floats2half2_rn(h0, h1);
            }
        }
    }
}

// ---------------------------------------------------------------------------
// down GEMM: 128 x 128 x 32, fp16, 4-stage cp.async, 2 CTAs/SM, ldmatrix A
// 256 threads, 8 warps (2M x 4N), warp tile 64x32; dynamic smem
// writes contribution rows to g_c (no atomics)
// ---------------------------------------------------------------------------
#define DN_S 4
#define DN_A_BYTES (128 * AW * 2)        // 10240
#define DN_B_BYTES (16 * BW * 4)         // 8704
#define DN_SMEM (DN_S * (DN_A_BYTES + DN_B_BYTES))   // 75776

__global__ void __launch_bounds__(256, 2)
down_mma() {
    extern __shared__ char dsm[];
    __half*  As = (__half*)dsm;                         // [DN_S][128*AW]
    __half2* Bd = (__half2*)(dsm + DN_S * DN_A_BYTES);  // [DN_S][16*BW]

    __shared__ int stok[128];

    int e   = blockIdx.z;
    int cnt = g_cnt[e];
    int m0  = blockIdx.y * 128;
    if (m0 >= cnt) return;
    int n0  = blockIdx.x * 128;

    int tid = threadIdx.x;
    if (tid < 128) {
        int m = m0 + tid;
        stok[tid] = (m < cnt) ? g_tok[e][m] : 0;
    }
    __syncthreads();

    const __half2* wdE = g_wdi + (size_t)e * F2 * DIM;
    const __half*  hE  = g_h + (size_t)e * T_TOK * FDIM;

    int wid  = tid >> 5, lane = tid & 31;
    int gid  = lane >> 2, tig = lane & 3;
    int warpM = wid & 1, warpN = wid >> 1;
    int wm = warpM * 64, wn = warpN * 32;

    int arow = tid >> 1, acol = (tid & 1) * 16;          // A: 2 chunks at acol, acol+8
    int bkr  = tid >> 4, bn = (tid & 15) * 8;            // B: 2 chunks
    int lrow = wm + (lane & 15), lchunk = (lane >> 4) * 8;

    const __half* hr0 = hE + (size_t)((m0 + arow) & 4095) * FDIM + acol;

    float c[4][4][4] = {};

    const int KT = FDIM / 32;    // 44

    // prologue
#pragma unroll
    for (int s = 0; s < DN_S - 1; s++) {
        int kb = s * 32, kb2 = s * 16;
        cp16(&As[s * 128 * AW + arow * AW + acol],     hr0 + kb);
        cp16(&As[s * 128 * AW + arow * AW + acol + 8], hr0 + kb + 8);
        cp16(&Bd[s * 16 * BW + bkr * BW + bn],     wdE + (size_t)(kb2 + bkr) * DIM + n0 + bn);
        cp16(&Bd[s * 16 * BW + bkr * BW + bn + 4], wdE + (size_t)(kb2 + bkr) * DIM + n0 + bn + 4);
        cp_commit();
    }

    for (int kt = 0; kt < KT; kt++) {
        cp_wait<DN_S - 2>();
        __syncthreads();

        int ln = kt + DN_S - 1;
        if (ln < KT) {
            int s = ln % DN_S;
            int kb = ln * 32, kb2 = ln * 16;
            cp16(&As[s * 128 * AW + arow * AW + acol],     hr0 + kb);
            cp16(&As[s * 128 * AW + arow * AW + acol + 8], hr0 + kb + 8);
            cp16(&Bd[s * 16 * BW + bkr * BW + bn],     wdE + (size_t)(kb2 + bkr) * DIM + n0 + bn);
            cp16(&Bd[s * 16 * BW + bkr * BW + bn + 4], wdE + (size_t)(kb2 + bkr) * DIM + n0 + bn + 4);
        }
        cp_commit();

        int cs = kt % DN_S;
        const __half*  Ac = As + cs * 128 * AW;
        const __half2* Dc = Bd + cs * 16 * BW;
#pragma unroll
        for (int ks = 0; ks < 2; ks++) {
            unsigned abase = (unsigned)__cvta_generic_to_shared(
                &Ac[lrow * AW + ks * 16 + lchunk]);
            unsigned a[4][4];
#pragma unroll
            for (int mi = 0; mi < 4; mi++)
                ldsm4(a[mi], abase + (unsigned)(mi * 16 * AW * 2));
#pragma unroll
            for (int ni = 0; ni < 4; ni++) {
                int nc = wn + ni * 8 + gid;
                unsigned b0 = *(const unsigned*)&Dc[(ks * 8 + tig    ) * BW + nc];
                unsigned b1 = *(const unsigned*)&Dc[(ks * 8 + tig + 4) * BW + nc];
#pragma unroll
                for (int mi = 0; mi < 4; mi++) {
                    mma_f16(c[mi][ni], a[mi], b0, b1);
                }
            }
        }
    }

    // epilogue: write contribution rows (plain stores, no atomics)
#pragma unroll
    for (int mi = 0; mi < 4; mi++) {
#pragma unroll
        for (int half = 0; half < 2; half++) {
            int lm = wm + mi * 16 + gid + half * 8;
            int m  = m0 + lm;
            if (m >= cnt) continue;
            int v = stok[lm];
            int tok = v & 4095, which = v >> 12;
            float* crow = &g_c[which][(size_t)tok * DIM + n0];
#pragma unroll
            for (int ni = 0; ni < 4; ni++) {
                int col = wn + ni * 8 + 2 * tig;
                float2 o;
                o.x = c[mi][ni][half * 2 + 0];
                o.y = c[mi][ni][half * 2 + 1];
                *(float2*)(crow + col) = o;
            }
        }
    }
}

// ---------------------------------------------------------------------------
// combine: out[t] = contrib[0][t] + contrib[1][t]  (fixed order, deterministic)
// ---------------------------------------------------------------------------
__global__ void combine_kernel(float* __restrict__ out) {
    size_t i = ((size_t)blockIdx.x * blockDim.x + threadIdx.x) * 4;
    float4 a = *(const float4*)&g_c[0][i];
    float4 b = *(const float4*)&g_c[1][i];
    float4 o;
    o.x = a.x + b.x; o.y = a.y + b.y; o.z = a.z + b.z; o.w = a.w + b.w;
    *(float4*)(out + i) = o;
}

// ---------------------------------------------------------------------------
extern "C" void kernel_launch(void* const* d_in, const int* in_sizes, int n_in,
                              void* d_out, int out_size) {
    const float* x  = (const float*)d_in[0];   // [T, D]
    const float* gw = (const float*)d_in[1];   // [E, D]
    const float* wg = (const float*)d_in[2];   // [E, D, F]
    const float* wu = (const float*)d_in[3];   // [E, D, F]
    const float* wd = (const float*)d_in[4];   // [E, F, D]
    float* out = (float*)d_out;

    cudaFuncSetAttribute(gateup_mma, cudaFuncAttributeMaxDynamicSharedMemorySize, GU_SMEM);
    cudaFuncSetAttribute(down_mma,   cudaFuncAttributeMaxDynamicSharedMemorySize, DN_SMEM);

    conv_gu<<<(NEXP * D2 * (FDIM / 4) + 255) / 256, 256>>>(wg, wu);
    conv_wd<<<(NEXP * F2 * (DIM / 4) + 255) / 256, 256>>>(wd);
    router_kernel<<<T_TOK, 128>>>(x, gw);

    dim3 g2(FDIM / 128, T_TOK / 128, NEXP);   // (11, 16, 8)
    gateup_mma<<<g2, 512, GU_SMEM>>>();

    dim3 g3(DIM / 128, T_TOK / 128, NEXP);    // (16, 16, 8)
    down_mma<<<g3, 256, DN_SMEM>>>();

    combine_kernel<<<(T_TOK * DIM) / (256 * 4), 256>>>(out);
}

// round 15
// speedup vs baseline: 1.0244x; 1.0244x over previous
#include <cuda_runtime.h>
#include <cuda_fp16.h>
#include <math.h>

#define T_TOK 2048
#define DIM   2048
#define NEXP  8
#define FDIM  1408
#define D2    (DIM / 2)     // 1024
#define F2    (FDIM / 2)    // 704

// ---- device scratch (no allocations allowed) ----
__device__ int     g_cnt[NEXP];
__device__ int     g_tok[NEXP][T_TOK];                      // tok | (which<<12)
__device__ float   g_wt [NEXP][T_TOK];
__device__ __half  g_xh [(size_t)T_TOK * DIM];              // x as half
__device__ __half2 g_wgi[(size_t)NEXP * D2 * FDIM];         // wg, k-pair interleaved
__device__ __half2 g_wui[(size_t)NEXP * D2 * FDIM];         // wu, k-pair interleaved
__device__ __half2 g_wdi[(size_t)NEXP * F2 * DIM];          // wd, k-pair interleaved
__device__ __half  g_h  [(size_t)NEXP * T_TOK * FDIM];      // SiLU(xWg)*(xWu)*w (half)
__device__ float   g_c  [2][(size_t)T_TOK * DIM];           // per-(token,which) down contribs

// ---------------------------------------------------------------------------
__device__ __forceinline__ void mma_f16(float* c, const unsigned* a,
                                        unsigned b0, unsigned b1) {
    asm volatile(
        "mma.sync.aligned.m16n8k16.row.col.f32.f16.f16.f32 "
        "{%0,%1,%2,%3}, {%4,%5,%6,%7}, {%8,%9}, {%0,%1,%2,%3};\n"
        : "+f"(c[0]), "+f"(c[1]), "+f"(c[2]), "+f"(c[3])
        : "r"(a[0]), "r"(a[1]), "r"(a[2]), "r"(a[3]), "r"(b0), "r"(b1));
}
__device__ __forceinline__ void ldsm4(unsigned* a, unsigned addr) {
    asm volatile("ldmatrix.sync.aligned.m8n8.x4.shared.b16 {%0,%1,%2,%3}, [%4];"
        : "=r"(a[0]), "=r"(a[1]), "=r"(a[2]), "=r"(a[3]) : "r"(addr));
}
__device__ __forceinline__ void cp16(void* sdst, const void* gsrc) {
    unsigned s = (unsigned)__cvta_generic_to_shared(sdst);
    asm volatile("cp.async.cg.shared.global [%0], [%1], 16;\n" :: "r"(s), "l"(gsrc));
}
__device__ __forceinline__ void cp_commit() { asm volatile("cp.async.commit_group;\n"); }
template <int N>
__device__ __forceinline__ void cp_wait() { asm volatile("cp.async.wait_group %0;\n" :: "n"(N)); }

// ---------------------------------------------------------------------------
// prep: merged weight conversion. Both streams have EXACTLY 11264 blocks of
// 256 threads (8*1024*352 == 8*704*512 == 2,883,584 uint4 items each).
// Interleave 1:1: even blockIdx -> gu stream, odd -> wd stream.
// ---------------------------------------------------------------------------
#define GU_BLOCKS (NEXP * D2 * (FDIM / 4) / 256)   // 11264
#define WD_BLOCKS (NEXP * F2 * (DIM / 4) / 256)    // 11264
#define PREP_BLOCKS (GU_BLOCKS + WD_BLOCKS)        // 22528

__global__ void prep_kernel(const float* __restrict__ wg,
                            const float* __restrict__ wu,
                            const float* __restrict__ wd) {
    if (blockIdx.x == 0 && threadIdx.x < NEXP) g_cnt[threadIdx.x] = 0;
    int sb = blockIdx.x >> 1;              // stream-local block id, 0..11263
    if ((blockIdx.x & 1) == 0) {
        // conv_gu work: wg/wu [E][D][F] fp32 -> [E][D/2][F] half2 (pair over D)
        int id = sb * 256 + threadIdx.x;
        int e   = id / (D2 * (FDIM / 4));
        int rem = id % (D2 * (FDIM / 4));
        int d2  = rem / (FDIM / 4);
        int f   = (rem % (FDIM / 4)) * 4;
        size_t ibase = ((size_t)e * DIM + 2 * d2) * FDIM + f;
        size_t obase = ((size_t)e * D2 + d2) * FDIM + f;
        {
            float4 a0 = *(const float4*)(wg + ibase);
            float4 a1 = *(const float4*)(wg + ibase + FDIM);
            __half2 h[4];
            h[0] = __floats2half2_rn(a0.x, a1.x);
            h[1] = __floats2half2_rn(a0.y, a1.y);
            h[2] = __floats2half2_rn(a0.z, a1.z);
            h[3] = __floats2half2_rn(a0.w, a1.w);
            *(uint4*)(g_wgi + obase) = *(uint4*)h;
        }
        {
            float4 a0 = *(const float4*)(wu + ibase);
            float4 a1 = *(const float4*)(wu + ibase + FDIM);
            __half2 h[4];
            h[0] = __floats2half2_rn(a0.x, a1.x);
            h[1] = __floats2half2_rn(a0.y, a1.y);
            h[2] = __floats2half2_rn(a0.z, a1.z);
            h[3] = __floats2half2_rn(a0.w, a1.w);
            *(uint4*)(g_wui + obase) = *(uint4*)h;
        }
    } else {
        // conv_wd work: wd [E][F][D] fp32 -> [E][F/2][D] half2 (pair over F)
        int id = sb * 256 + threadIdx.x;
        int e   = id / (F2 * (DIM / 4));
        int rem = id % (F2 * (DIM / 4));
        int f2  = rem / (DIM / 4);
        int d   = (rem % (DIM / 4)) * 4;
        size_t ibase = ((size_t)e * FDIM + 2 * f2) * DIM + d;
        float4 a0 = *(const float4*)(wd + ibase);
        float4 a1 = *(const float4*)(wd + ibase + DIM);
        __half2 h[4];
        h[0] = __floats2half2_rn(a0.x, a1.x);
        h[1] = __floats2half2_rn(a0.y, a1.y);
        h[2] = __floats2half2_rn(a0.z, a1.z);
        h[3] = __floats2half2_rn(a0.w, a1.w);
        *(uint4*)(g_wdi + ((size_t)e * F2 + f2) * DIM + d) = *(uint4*)h;
    }
}

// ---------------------------------------------------------------------------
// router: logits -> softmax -> top2 -> renorm -> scatter; fuses x->half convert
// ---------------------------------------------------------------------------
__global__ void router_kernel(const float* __restrict__ x,
                              const float* __restrict__ gw) {
    int t   = blockIdx.x;
    int tid = threadIdx.x;

    float p[NEXP];
#pragma unroll
    for (int e = 0; e < NEXP; e++) p[e] = 0.0f;

    const float* xr = x + (size_t)t * DIM;
    __half* xh = g_xh + (size_t)t * DIM;
#pragma unroll
    for (int it = 0; it < DIM / 512; it++) {
        int d = (it * 128 + tid) * 4;
        float4 xv = *(const float4*)(xr + d);
        __half2 hv[2];
        hv[0] = __floats2half2_rn(xv.x, xv.y);
        hv[1] = __floats2half2_rn(xv.z, xv.w);
        *(uint2*)(xh + d) = *(uint2*)hv;
#pragma unroll
        for (int e = 0; e < NEXP; e++) {
            float4 gv = *(const float4*)(gw + e * DIM + d);
            p[e] += xv.x * gv.x + xv.y * gv.y + xv.z * gv.z + xv.w * gv.w;
        }
    }

    __shared__ float sm[NEXP][128];
#pragma unroll
    for (int e = 0; e < NEXP; e++) sm[e][tid] = p[e];
    __syncthreads();

    for (int s = 64; s > 0; s >>= 1) {
        if (tid < s) {
#pragma unroll
            for (int e = 0; e < NEXP; e++) sm[e][tid] += sm[e][tid + s];
        }
        __syncthreads();
    }

    if (tid == 0) {
        float lg[NEXP];
        float mx = -1e30f;
#pragma unroll
        for (int e = 0; e < NEXP; e++) { lg[e] = sm[e][0]; mx = fmaxf(mx, lg[e]); }
        float pr[NEXP];
#pragma unroll
        for (int e = 0; e < NEXP; e++) pr[e] = expf(lg[e] - mx);
        int e0 = 0;
#pragma unroll
        for (int e = 1; e < NEXP; e++) if (pr[e] > pr[e0]) e0 = e;
        int e1 = (e0 == 0) ? 1 : 0;
#pragma unroll
        for (int e = 0; e < NEXP; e++)
            if (e != e0 && pr[e] > pr[e1]) e1 = e;
        float denom = pr[e0] + pr[e1];
        float w0 = pr[e0] / denom;
        float w1 = pr[e1] / denom;
        int p0 = atomicAdd(&g_cnt[e0], 1);
        g_tok[e0][p0] = t;          g_wt[e0][p0] = w0;   // which = 0
        int p1 = atomicAdd(&g_cnt[e1], 1);
        g_tok[e1][p1] = t | 4096;   g_wt[e1][p1] = w1;   // which = 1
    }
}

// ---------------------------------------------------------------------------
#define AW 40    // A row: 40 halves (80B) -> LDSM conflict-free
#define BW 136   // B row: 136 half2 -> stride mod 32 == 8, conflict-free

// ---------------------------------------------------------------------------
// gate+up GEMM: 128 x 128(per matrix) x 32, fp16, 3-stage cp.async, ldmatrix A
// 512 threads, 16 warps (2M x 8N), warp tile 64x16 per matrix; dynamic smem
// ---------------------------------------------------------------------------
#define GU_S 3
#define GU_A_BYTES (128 * AW * 2)        // 10240
#define GU_B_BYTES (16 * BW * 4)         // 8704
#define GU_SMEM (GU_S * (GU_A_BYTES + 2 * GU_B_BYTES))   // 82944

__global__ void __launch_bounds__(512, 1)
gateup_mma() {
    extern __shared__ char dsm[];
    __half*  As = (__half*)dsm;                                       // [GU_S][128*AW]
    __half2* Bg = (__half2*)(dsm + GU_S * GU_A_BYTES);                // [GU_S][16*BW]
    __half2* Bu = (__half2*)(dsm + GU_S * (GU_A_BYTES + GU_B_BYTES)); // [GU_S][16*BW]

    __shared__ int   stok[128];
    __shared__ float swt[128];

    int e   = blockIdx.z;
    int cnt = g_cnt[e];
    int m0  = blockIdx.y * 128;
    if (m0 >= cnt) return;
    int n0  = blockIdx.x * 128;

    int tid = threadIdx.x;
    if (tid < 128) {
        int m = m0 + tid;
        int v = (m < cnt) ? g_tok[e][m] : 0;
        stok[tid] = v & 4095;
        swt[tid]  = (m < cnt) ? g_wt[e][m] : 0.0f;
    }
    __syncthreads();

    const __half2* wgE = g_wgi + (size_t)e * D2 * FDIM;
    const __half2* wuE = g_wui + (size_t)e * D2 * FDIM;

    int wid  = tid >> 5, lane = tid & 31;
    int gid  = lane >> 2, tig = lane & 3;
    int warpM = wid & 1, warpN = wid >> 1;       // 2 x 8 warps
    int wm = warpM * 64, wn = warpN * 16;

    int arow = tid >> 2, acol = (tid & 3) * 8;           // A: 128 rows x 4 chunks
    int bkr  = tid >> 5, bn = (tid & 31) * 4;            // B: 16 rows x 32 chunks

    int lrow = wm + (lane & 15), lchunk = (lane >> 4) * 8;

    const __half* xr0 = g_xh + (size_t)stok[arow] * DIM + acol;

    float cg[4][2][4] = {}, cu[4][2][4] = {};

    const int KT = DIM / 32;     // 64

    // prologue
#pragma unroll
    for (int s = 0; s < GU_S - 1; s++) {
        int kb = s * 32, kb2 = s * 16;
        cp16(&As[s * 128 * AW + arow * AW + acol], xr0 + kb);
        cp16(&Bg[s * 16 * BW + bkr * BW + bn], wgE + (size_t)(kb2 + bkr) * FDIM + n0 + bn);
        cp16(&Bu[s * 16 * BW + bkr * BW + bn], wuE + (size_t)(kb2 + bkr) * FDIM + n0 + bn);
        cp_commit();
    }

    for (int kt = 0; kt < KT; kt++) {
        cp_wait<GU_S - 2>();
        __syncthreads();

        int ln = kt + GU_S - 1;
        if (ln < KT) {
            int s = ln % GU_S;
            int kb = ln * 32, kb2 = ln * 16;
            cp16(&As[s * 128 * AW + arow * AW + acol], xr0 + kb);
            cp16(&Bg[s * 16 * BW + bkr * BW + bn], wgE + (size_t)(kb2 + bkr) * FDIM + n0 + bn);
            cp16(&Bu[s * 16 * BW + bkr * BW + bn], wuE + (size_t)(kb2 + bkr) * FDIM + n0 + bn);
        }
        cp_commit();

        int cs = kt % GU_S;
        const __half*  Ac = As + cs * 128 * AW;
        const __half2* Gc = Bg + cs * 16 * BW;
        const __half2* Uc = Bu + cs * 16 * BW;
#pragma unroll
        for (int ks = 0; ks < 2; ks++) {
            unsigned abase = (unsigned)__cvta_generic_to_shared(
                &Ac[lrow * AW + ks * 16 + lchunk]);
            unsigned a[4][4];
#pragma unroll
            for (int mi = 0; mi < 4; mi++)
                ldsm4(a[mi], abase + (unsigned)(mi * 16 * AW * 2));
#pragma unroll
            for (int ni = 0; ni < 2; ni++) {
                int nc = wn + ni * 8 + gid;
                unsigned bg0 = *(const unsigned*)&Gc[(ks * 8 + tig    ) * BW + nc];
                unsigned bg1 = *(const unsigned*)&Gc[(ks * 8 + tig + 4) * BW + nc];
                unsigned bu0 = *(const unsigned*)&Uc[(ks * 8 + tig    ) * BW + nc];
                unsigned bu1 = *(const unsigned*)&Uc[(ks * 8 + tig + 4) * BW + nc];
#pragma unroll
                for (int mi = 0; mi < 4; mi++) {
                    mma_f16(cg[mi][ni], a[mi], bg0, bg1);
                    mma_f16(cu[mi][ni], a[mi], bu0, bu1);
                }
            }
        }
    }

    // epilogue: SiLU(g)*u*w -> g_h (half)
#pragma unroll
    for (int mi = 0; mi < 4; mi++) {
#pragma unroll
        for (int half = 0; half < 2; half++) {
            int lm = wm + mi * 16 + gid + half * 8;
            int m  = m0 + lm;
            if (m >= cnt) continue;
            float w = swt[lm];
            __half* hrow = g_h + ((size_t)e * T_TOK + m) * FDIM + n0;
#pragma unroll
            for (int ni = 0; ni < 2; ni++) {
                int col = wn + ni * 8 + 2 * tig;
                float g0 = cg[mi][ni][half * 2 + 0], g1 = cg[mi][ni][half * 2 + 1];
                float u0 = cu[mi][ni][half * 2 + 0], u1 = cu[mi][ni][half * 2 + 1];
                float h0 = (g0 / (1.0f + __expf(-g0))) * u0 * w;
                float h1 = (g1 / (1.0f + __expf(-g1))) * u1 * w;
                *(__half2*)(hrow + col) = __floats2half2_rn(h0, h1);
            }
        }
    }
}

// ---------------------------------------------------------------------------
// down GEMM: 128 x 128 x 32, fp16, 3-stage cp.async, 2 CTAs/SM, ldmatrix A
// 256 threads, 8 warps (2M x 4N), warp tile 64x32; dynamic smem
// writes contribution rows to g_c (no atomics)
// ---------------------------------------------------------------------------
#define DN_S 3
#define DN_A_BYTES (128 * AW * 2)        // 10240
#define DN_B_BYTES (16 * BW * 4)         // 8704
#define DN_SMEM (DN_S * (DN_A_BYTES + DN_B_BYTES))   // 56832

__global__ void __launch_bounds__(256, 2)
down_mma() {
    extern __shared__ char dsm[];
    __half*  As = (__half*)dsm;                         // [DN_S][128*AW]
    __half2* Bd = (__half2*)(dsm + DN_S * DN_A_BYTES);  // [DN_S][16*BW]

    __shared__ int stok[128];

    int e   = blockIdx.z;
    int cnt = g_cnt[e];
    int m0  = blockIdx.y * 128;
    if (m0 >= cnt) return;
    int n0  = blockIdx.x * 128;

    int tid = threadIdx.x;
    if (tid < 128) {
        int m = m0 + tid;
        stok[tid] = (m < cnt) ? g_tok[e][m] : 0;
    }
    __syncthreads();

    const __half2* wdE = g_wdi + (size_t)e * F2 * DIM;
    const __half*  hE  = g_h + (size_t)e * T_TOK * FDIM;

    int wid  = tid >> 5, lane = tid & 31;
    int gid  = lane >> 2, tig = lane & 3;
    int warpM = wid & 1, warpN = wid >> 1;
    int wm = warpM * 64, wn = warpN * 32;

    int arow = tid >> 1, acol = (tid & 1) * 16;          // A: 2 chunks at acol, acol+8
    int bkr  = tid >> 4, bn = (tid & 15) * 8;            // B: 2 chunks
    int lrow = wm + (lane & 15), lchunk = (lane >> 4) * 8;

    const __half* hr0 = hE + (size_t)((m0 + arow) & 4095) * FDIM + acol;

    float c[4][4][4] = {};

    const int KT = FDIM / 32;    // 44

    // prologue
#pragma unroll
    for (int s = 0; s < DN_S - 1; s++) {
        int kb = s * 32, kb2 = s * 16;
        cp16(&As[s * 128 * AW + arow * AW + acol],     hr0 + kb);
        cp16(&As[s * 128 * AW + arow * AW + acol + 8], hr0 + kb + 8);
        cp16(&Bd[s * 16 * BW + bkr * BW + bn],     wdE + (size_t)(kb2 + bkr) * DIM + n0 + bn);
        cp16(&Bd[s * 16 * BW + bkr * BW + bn + 4], wdE + (size_t)(kb2 + bkr) * DIM + n0 + bn + 4);
        cp_commit();
    }

    for (int kt = 0; kt < KT; kt++) {
        cp_wait<DN_S - 2>();
        __syncthreads();

        int ln = kt + DN_S - 1;
        if (ln < KT) {
            int s = ln % DN_S;
            int kb = ln * 32, kb2 = ln * 16;
            cp16(&As[s * 128 * AW + arow * AW + acol],     hr0 + kb);
            cp16(&As[s * 128 * AW + arow * AW + acol + 8], hr0 + kb + 8);
            cp16(&Bd[s * 16 * BW + bkr * BW + bn],     wdE + (size_t)(kb2 + bkr) * DIM + n0 + bn);
            cp16(&Bd[s * 16 * BW + bkr * BW + bn + 4], wdE + (size_t)(kb2 + bkr) * DIM + n0 + bn + 4);
        }
        cp_commit();

        int cs = kt % DN_S;
        const __half*  Ac = As + cs * 128 * AW;
        const __half2* Dc = Bd + cs * 16 * BW;
#pragma unroll
        for (int ks = 0; ks < 2; ks++) {
            unsigned abase = (unsigned)__cvta_generic_to_shared(
                &Ac[lrow * AW + ks * 16 + lchunk]);
            unsigned a[4][4];
#pragma unroll
            for (int mi = 0; mi < 4; mi++)
                ldsm4(a[mi], abase + (unsigned)(mi * 16 * AW * 2));
#pragma unroll
            for (int ni = 0; ni < 4; ni++) {
                int nc = wn + ni * 8 + gid;
                unsigned b0 = *(const unsigned*)&Dc[(ks * 8 + tig    ) * BW + nc];
                unsigned b1 = *(const unsigned*)&Dc[(ks * 8 + tig + 4) * BW + nc];
#pragma unroll
                for (int mi = 0; mi < 4; mi++) {
                    mma_f16(c[mi][ni], a[mi], b0, b1);
                }
            }
        }
    }

    // epilogue: write contribution rows (plain stores, no atomics)
#pragma unroll
    for (int mi = 0; mi < 4; mi++) {
#pragma unroll
        for (int half = 0; half < 2; half++) {
            int lm = wm + mi * 16 + gid + half * 8;
            int m  = m0 + lm;
            if (m >= cnt) continue;
            int v = stok[lm];
            int tok = v & 4095, which = v >> 12;
            float* crow = &g_c[which][(size_t)tok * DIM + n0];
#pragma unroll
            for (int ni = 0; ni < 4; ni++) {
                int col = wn + ni * 8 + 2 * tig;
                float2 o;
                o.x = c[mi][ni][half * 2 + 0];
                o.y = c[mi][ni][half * 2 + 1];
                *(float2*)(crow + col) = o;
            }
        }
    }
}

// ---------------------------------------------------------------------------
// combine: out[t] = contrib[0][t] + contrib[1][t]  (fixed order, deterministic)
// ---------------------------------------------------------------------------
__global__ void combine_kernel(float* __restrict__ out) {
    size_t i = ((size_t)blockIdx.x * blockDim.x + threadIdx.x) * 4;
    float4 a = *(const float4*)&g_c[0][i];
    float4 b = *(const float4*)&g_c[1][i];
    float4 o;
    o.x = a.x + b.x; o.y = a.y + b.y; o.z = a.z + b.z; o.w = a.w + b.w;
    *(float4*)(out + i) = o;
}

// ---------------------------------------------------------------------------
extern "C" void kernel_launch(void* const* d_in, const int* in_sizes, int n_in,
                              void* d_out, int out_size) {
    const float* x  = (const float*)d_in[0];   // [T, D]
    const float* gw = (const float*)d_in[1];   // [E, D]
    const float* wg = (const float*)d_in[2];   // [E, D, F]
    const float* wu = (const float*)d_in[3];   // [E, D, F]
    const float* wd = (const float*)d_in[4];   // [E, F, D]
    float* out = (float*)d_out;

    cudaFuncSetAttribute(gateup_mma, cudaFuncAttributeMaxDynamicSharedMemorySize, GU_SMEM);
    cudaFuncSetAttribute(down_mma,   cudaFuncAttributeMaxDynamicSharedMemorySize, DN_SMEM);

    prep_kernel<<<PREP_BLOCKS, 256>>>(wg, wu, wd);
    router_kernel<<<T_TOK, 128>>>(x, gw);

    dim3 g2(FDIM / 128, T_TOK / 128, NEXP);   // (11, 16, 8)
    gateup_mma<<<g2, 512, GU_SMEM>>>();

    dim3 g3(DIM / 128, T_TOK / 128, NEXP);    // (16, 16, 8)
    down_mma<<<g3, 256, DN_SMEM>>>();

    combine_kernel<<<(T_TOK * DIM) / (256 * 4), 256>>>(out);
}

// round 16
// speedup vs baseline: 1.0430x; 1.0182x over previous
#include <cuda_runtime.h>
#include <cuda_fp16.h>
#include <math.h>

#define T_TOK 2048
#define DIM   2048
#define NEXP  8
#define FDIM  1408
#define D2    (DIM / 2)     // 1024
#define F2    (FDIM / 2)    // 704

// ---- device scratch (no allocations allowed) ----
__device__ int     g_cnt[NEXP];                             // zero at replay start (BSS / combine reset)
__device__ int     g_tok[NEXP][T_TOK];                      // tok | (which<<12)
__device__ float   g_wt [NEXP][T_TOK];
__device__ __half  g_xh [(size_t)T_TOK * DIM];              // x as half
__device__ __half2 g_wgi[(size_t)NEXP * D2 * FDIM];         // wg, k-pair interleaved
__device__ __half2 g_wui[(size_t)NEXP * D2 * FDIM];         // wu, k-pair interleaved
__device__ __half2 g_wdi[(size_t)NEXP * F2 * DIM];          // wd, k-pair interleaved
__device__ __half  g_h  [(size_t)NEXP * T_TOK * FDIM];      // SiLU(xWg)*(xWu)*w (half)
__device__ float   g_c  [2][(size_t)T_TOK * DIM];           // per-(token,which) down contribs

// ---------------------------------------------------------------------------
__device__ __forceinline__ void mma_f16(float* c, const unsigned* a,
                                        unsigned b0, unsigned b1) {
    asm volatile(
        "mma.sync.aligned.m16n8k16.row.col.f32.f16.f16.f32 "
        "{%0,%1,%2,%3}, {%4,%5,%6,%7}, {%8,%9}, {%0,%1,%2,%3};\n"
        : "+f"(c[0]), "+f"(c[1]), "+f"(c[2]), "+f"(c[3])
        : "r"(a[0]), "r"(a[1]), "r"(a[2]), "r"(a[3]), "r"(b0), "r"(b1));
}
__device__ __forceinline__ void ldsm4(unsigned* a, unsigned addr) {
    asm volatile("ldmatrix.sync.aligned.m8n8.x4.shared.b16 {%0,%1,%2,%3}, [%4];"
        : "=r"(a[0]), "=r"(a[1]), "=r"(a[2]), "=r"(a[3]) : "r"(addr));
}
__device__ __forceinline__ void cp16(void* sdst, const void* gsrc) {
    unsigned s = (unsigned)__cvta_generic_to_shared(sdst);
    asm volatile("cp.async.cg.shared.global [%0], [%1], 16;\n" :: "r"(s), "l"(gsrc));
}
__device__ __forceinline__ void cp_commit() { asm volatile("cp.async.commit_group;\n"); }
template <int N>
__device__ __forceinline__ void cp_wait() { asm volatile("cp.async.wait_group %0;\n" :: "n"(N)); }

// ---------------------------------------------------------------------------
// prep_router: single launch doing router (blocks 0..2047) and weight
// conversion (blocks 2048..24575). g_cnt is zero on entry (BSS at first run;
// reset by combine_kernel at the end of every replay).
// ---------------------------------------------------------------------------
#define GU_BLOCKS (NEXP * D2 * (FDIM / 4) / 256)   // 11264
#define WD_BLOCKS (NEXP * F2 * (DIM / 4) / 256)    // 11264
#define PR_BLOCKS (T_TOK + GU_BLOCKS + WD_BLOCKS)  // 24576

__global__ void __launch_bounds__(256)
prep_router(const float* __restrict__ x,  const float* __restrict__ gw,
            const float* __restrict__ wg, const float* __restrict__ wu,
            const float* __restrict__ wd) {
    int tid = threadIdx.x;
    if (blockIdx.x < T_TOK) {
        // ---- router for token t (fuses x -> half conversion) ----
        int t = blockIdx.x;
        float p[NEXP];
#pragma unroll
        for (int e = 0; e < NEXP; e++) p[e] = 0.0f;

        const float* xr = x + (size_t)t * DIM;
        __half* xh = g_xh + (size_t)t * DIM;
#pragma unroll
        for (int it = 0; it < DIM / 1024; it++) {
            int d = (it * 256 + tid) * 4;
            float4 xv = *(const float4*)(xr + d);
            __half2 hv[2];
            hv[0] = __floats2half2_rn(xv.x, xv.y);
            hv[1] = __floats2half2_rn(xv.z, xv.w);
            *(uint2*)(xh + d) = *(uint2*)hv;
#pragma unroll
            for (int e = 0; e < NEXP; e++) {
                float4 gv = *(const float4*)(gw + e * DIM + d);
                p[e] += xv.x * gv.x + xv.y * gv.y + xv.z * gv.z + xv.w * gv.w;
            }
        }

        __shared__ float sm[NEXP][256];
#pragma unroll
        for (int e = 0; e < NEXP; e++) sm[e][tid] = p[e];
        __syncthreads();

        for (int s = 128; s > 0; s >>= 1) {
            if (tid < s) {
#pragma unroll
                for (int e = 0; e < NEXP; e++) sm[e][tid] += sm[e][tid + s];
            }
            __syncthreads();
        }

        if (tid == 0) {
            float lg[NEXP];
            float mx = -1e30f;
#pragma unroll
            for (int e = 0; e < NEXP; e++) { lg[e] = sm[e][0]; mx = fmaxf(mx, lg[e]); }
            float pr[NEXP];
#pragma unroll
            for (int e = 0; e < NEXP; e++) pr[e] = expf(lg[e] - mx);
            int e0 = 0;
#pragma unroll
            for (int e = 1; e < NEXP; e++) if (pr[e] > pr[e0]) e0 = e;
            int e1 = (e0 == 0) ? 1 : 0;
#pragma unroll
            for (int e = 0; e < NEXP; e++)
                if (e != e0 && pr[e] > pr[e1]) e1 = e;
            float denom = pr[e0] + pr[e1];
            float w0 = pr[e0] / denom;
            float w1 = pr[e1] / denom;
            int p0 = atomicAdd(&g_cnt[e0], 1);
            g_tok[e0][p0] = t;          g_wt[e0][p0] = w0;   // which = 0
            int p1 = atomicAdd(&g_cnt[e1], 1);
            g_tok[e1][p1] = t | 4096;   g_wt[e1][p1] = w1;   // which = 1
        }
        return;
    }

    // ---- weight conversion; both streams have exactly 11264 blocks ----
    int pb = blockIdx.x - T_TOK;
    int sb = pb >> 1;
    if ((pb & 1) == 0) {
        // wg/wu: [E][D][F] fp32 -> [E][D/2][F] half2 (pair over D)
        int id = sb * 256 + tid;
        int e   = id / (D2 * (FDIM / 4));
        int rem = id % (D2 * (FDIM / 4));
        int d2  = rem / (FDIM / 4);
        int f   = (rem % (FDIM / 4)) * 4;
        size_t ibase = ((size_t)e * DIM + 2 * d2) * FDIM + f;
        size_t obase = ((size_t)e * D2 + d2) * FDIM + f;
        {
            float4 a0 = *(const float4*)(wg + ibase);
            float4 a1 = *(const float4*)(wg + ibase + FDIM);
            __half2 h[4];
            h[0] = __floats2half2_rn(a0.x, a1.x);
            h[1] = __floats2half2_rn(a0.y, a1.y);
            h[2] = __floats2half2_rn(a0.z, a1.z);
            h[3] = __floats2half2_rn(a0.w, a1.w);
            *(uint4*)(g_wgi + obase) = *(uint4*)h;
        }
        {
            float4 a0 = *(const float4*)(wu + ibase);
            float4 a1 = *(const float4*)(wu + ibase + FDIM);
            __half2 h[4];
            h[0] = __floats2half2_rn(a0.x, a1.x);
            h[1] = __floats2half2_rn(a0.y, a1.y);
            h[2] = __floats2half2_rn(a0.z, a1.z);
            h[3] = __floats2half2_rn(a0.w, a1.w);
            *(uint4*)(g_wui + obase) = *(uint4*)h;
        }
    } else {
        // wd: [E][F][D] fp32 -> [E][F/2][D] half2 (pair over F)
        int id = sb * 256 + tid;
        int e   = id / (F2 * (DIM / 4));
        int rem = id % (F2 * (DIM / 4));
        int f2  = rem / (DIM / 4);
        int d   = (rem % (DIM / 4)) * 4;
        size_t ibase = ((size_t)e * FDIM + 2 * f2) * DIM + d;
        float4 a0 = *(const float4*)(wd + ibase);
        float4 a1 = *(const float4*)(wd + ibase + DIM);
        __half2 h[4];
        h[0] = __floats2half2_rn(a0.x, a1.x);
        h[1] = __floats2half2_rn(a0.y, a1.y);
        h[2] = __floats2half2_rn(a0.z, a1.z);
        h[3] = __floats2half2_rn(a0.w, a1.w);
        *(uint4*)(g_wdi + ((size_t)e * F2 + f2) * DIM + d) = *(uint4*)h;
    }
}

// ---------------------------------------------------------------------------
#define AW 40    // A row: 40 halves (80B) -> LDSM conflict-free
#define BW 136   // B row: 136 half2 -> stride mod 32 == 8, conflict-free

// ---------------------------------------------------------------------------
// gate+up GEMM: 128 x 128(per matrix) x 32, fp16, 3-stage cp.async, ldmatrix A
// 512 threads, 16 warps (2M x 8N), warp tile 64x16 per matrix; dynamic smem
// ---------------------------------------------------------------------------
#define GU_S 3
#define GU_A_BYTES (128 * AW * 2)        // 10240
#define GU_B_BYTES (16 * BW * 4)         // 8704
#define GU_SMEM (GU_S * (GU_A_BYTES + 2 * GU_B_BYTES))   // 82944

__global__ void __launch_bounds__(512, 1)
gateup_mma() {
    extern __shared__ char dsm[];
    __half*  As = (__half*)dsm;                                       // [GU_S][128*AW]
    __half2* Bg = (__half2*)(dsm + GU_S * GU_A_BYTES);                // [GU_S][16*BW]
    __half2* Bu = (__half2*)(dsm + GU_S * (GU_A_BYTES + GU_B_BYTES)); // [GU_S][16*BW]

    __shared__ int   stok[128];
    __shared__ float swt[128];

    int e   = blockIdx.z;
    int cnt = g_cnt[e];
    int m0  = blockIdx.y * 128;
    if (m0 >= cnt) return;
    int n0  = blockIdx.x * 128;

    int tid = threadIdx.x;
    if (tid < 128) {
        int m = m0 + tid;
        int v = (m < cnt) ? g_tok[e][m] : 0;
        stok[tid] = v & 4095;
        swt[tid]  = (m < cnt) ? g_wt[e][m] : 0.0f;
    }
    __syncthreads();

    const __half2* wgE = g_wgi + (size_t)e * D2 * FDIM;
    const __half2* wuE = g_wui + (size_t)e * D2 * FDIM;

    int wid  = tid >> 5, lane = tid & 31;
    int gid  = lane >> 2, tig = lane & 3;
    int warpM = wid & 1, warpN = wid >> 1;       // 2 x 8 warps
    int wm = warpM * 64, wn = warpN * 16;

    int arow = tid >> 2, acol = (tid & 3) * 8;           // A: 128 rows x 4 chunks
    int bkr  = tid >> 5, bn = (tid & 31) * 4;            // B: 16 rows x 32 chunks

    int lrow = wm + (lane & 15), lchunk = (lane >> 4) * 8;

    const __half* xr0 = g_xh + (size_t)stok[arow] * DIM + acol;

    float cg[4][2][4] = {}, cu[4][2][4] = {};

    const int KT = DIM / 32;     // 64

    // prologue
#pragma unroll
    for (int s = 0; s < GU_S - 1; s++) {
        int kb = s * 32, kb2 = s * 16;
        cp16(&As[s * 128 * AW + arow * AW + acol], xr0 + kb);
        cp16(&Bg[s * 16 * BW + bkr * BW + bn], wgE + (size_t)(kb2 + bkr) * FDIM + n0 + bn);
        cp16(&Bu[s * 16 * BW + bkr * BW + bn], wuE + (size_t)(kb2 + bkr) * FDIM + n0 + bn);
        cp_commit();
    }

    for (int kt = 0; kt < KT; kt++) {
        cp_wait<GU_S - 2>();
        __syncthreads();

        int ln = kt + GU_S - 1;
        if (ln < KT) {
            int s = ln % GU_S;
            int kb = ln * 32, kb2 = ln * 16;
            cp16(&As[s * 128 * AW + arow * AW + acol], xr0 + kb);
            cp16(&Bg[s * 16 * BW + bkr * BW + bn], wgE + (size_t)(kb2 + bkr) * FDIM + n0 + bn);
            cp16(&Bu[s * 16 * BW + bkr * BW + bn], wuE + (size_t)(kb2 + bkr) * FDIM + n0 + bn);
        }
        cp_commit();

        int cs = kt % GU_S;
        const __half*  Ac = As + cs * 128 * AW;
        const __half2* Gc = Bg + cs * 16 * BW;
        const __half2* Uc = Bu + cs * 16 * BW;
#pragma unroll
        for (int ks = 0; ks < 2; ks++) {
            unsigned abase = (unsigned)__cvta_generic_to_shared(
                &Ac[lrow * AW + ks * 16 + lchunk]);
            unsigned a[4][4];
#pragma unroll
            for (int mi = 0; mi < 4; mi++)
                ldsm4(a[mi], abase + (unsigned)(mi * 16 * AW * 2));
#pragma unroll
            for (int ni = 0; ni < 2; ni++) {
                int nc = wn + ni * 8 + gid;
                unsigned bg0 = *(const unsigned*)&Gc[(ks * 8 + tig    ) * BW + nc];
                unsigned bg1 = *(const unsigned*)&Gc[(ks * 8 + tig + 4) * BW + nc];
                unsigned bu0 = *(const unsigned*)&Uc[(ks * 8 + tig    ) * BW + nc];
                unsigned bu1 = *(const unsigned*)&Uc[(ks * 8 + tig + 4) * BW + nc];
#pragma unroll
                for (int mi = 0; mi < 4; mi++) {
                    mma_f16(cg[mi][ni], a[mi], bg0, bg1);
                    mma_f16(cu[mi][ni], a[mi], bu0, bu1);
                }
            }
        }
    }

    // epilogue: SiLU(g)*u*w -> g_h (half)
#pragma unroll
    for (int mi = 0; mi < 4; mi++) {
#pragma unroll
        for (int half = 0; half < 2; half++) {
            int lm = wm + mi * 16 + gid + half * 8;
            int m  = m0 + lm;
            if (m >= cnt) continue;
            float w = swt[lm];
            __half* hrow = g_h + ((size_t)e * T_TOK + m) * FDIM + n0;
#pragma unroll
            for (int ni = 0; ni < 2; ni++) {
                int col = wn + ni * 8 + 2 * tig;
                float g0 = cg[mi][ni][half * 2 + 0], g1 = cg[mi][ni][half * 2 + 1];
                float u0 = cu[mi][ni][half * 2 + 0], u1 = cu[mi][ni][half * 2 + 1];
                float h0 = (g0 / (1.0f + __expf(-g0))) * u0 * w;
                float h1 = (g1 / (1.0f + __expf(-g1))) * u1 * w;
                *(__half2*)(hrow + col) = __floats2half2_rn(h0, h1);
            }
        }
    }
}

// ---------------------------------------------------------------------------
// down GEMM: 128 x 128 x 32, fp16, 3-stage cp.async, 2 CTAs/SM, ldmatrix A
// 256 threads, 8 warps (2M x 4N), warp tile 64x32; dynamic smem
// writes contribution rows to g_c (no atomics)
// ---------------------------------------------------------------------------
#define DN_S 3
#define DN_A_BYTES (128 * AW * 2)        // 10240
#define DN_B_BYTES (16 * BW * 4)         // 8704
#define DN_SMEM (DN_S * (DN_A_BYTES + DN_B_BYTES))   // 56832

__global__ void __launch_bounds__(256, 2)
down_mma() {
    extern __shared__ char dsm[];
    __half*  As = (__half*)dsm;                         // [DN_S][128*AW]
    __half2* Bd = (__half2*)(dsm + DN_S * DN_A_BYTES);  // [DN_S][16*BW]

    __shared__ int stok[128];

    int e   = blockIdx.z;
    int cnt = g_cnt[e];
    int m0  = blockIdx.y * 128;
    if (m0 >= cnt) return;
    int n0  = blockIdx.x * 128;

    int tid = threadIdx.x;
    if (tid < 128) {
        int m = m0 + tid;
        stok[tid] = (m < cnt) ? g_tok[e][m] : 0;
    }
    __syncthreads();

    const __half2* wdE = g_wdi + (size_t)e * F2 * DIM;
    const __half*  hE  = g_h + (size_t)e * T_TOK * FDIM;

    int wid  = tid >> 5, lane = tid & 31;
    int gid  = lane >> 2, tig = lane & 3;
    int warpM = wid & 1, warpN = wid >> 1;
    int wm = warpM * 64, wn = warpN * 32;

    int arow = tid >> 1, acol = (tid & 1) * 16;          // A: 2 chunks at acol, acol+8
    int bkr  = tid >> 4, bn = (tid & 15) * 8;            // B: 2 chunks
    int lrow = wm + (lane & 15), lchunk = (lane >> 4) * 8;

    const __half* hr0 = hE + (size_t)((m0 + arow) & 4095) * FDIM + acol;

    float c[4][4][4] = {};

    const int KT = FDIM / 32;    // 44

    // prologue
#pragma unroll
    for (int s = 0; s < DN_S - 1; s++) {
        int kb = s * 32, kb2 = s * 16;
        cp16(&As[s * 128 * AW + arow * AW + acol],     hr0 + kb);
        cp16(&As[s * 128 * AW + arow * AW + acol + 8], hr0 + kb + 8);
        cp16(&Bd[s * 16 * BW + bkr * BW + bn],     wdE + (size_t)(kb2 + bkr) * DIM + n0 + bn);
        cp16(&Bd[s * 16 * BW + bkr * BW + bn + 4], wdE + (size_t)(kb2 + bkr) * DIM + n0 + bn + 4);
        cp_commit();
    }

    for (int kt = 0; kt < KT; kt++) {
        cp_wait<DN_S - 2>();
        __syncthreads();

        int ln = kt + DN_S - 1;
        if (ln < KT) {
            int s = ln % DN_S;
            int kb = ln * 32, kb2 = ln * 16;
            cp16(&As[s * 128 * AW + arow * AW + acol],     hr0 + kb);
            cp16(&As[s * 128 * AW + arow * AW + acol + 8], hr0 + kb + 8);
            cp16(&Bd[s * 16 * BW + bkr * BW + bn],     wdE + (size_t)(kb2 + bkr) * DIM + n0 + bn);
            cp16(&Bd[s * 16 * BW + bkr * BW + bn + 4], wdE + (size_t)(kb2 + bkr) * DIM + n0 + bn + 4);
        }
        cp_commit();

        int cs = kt % DN_S;
        const __half*  Ac = As + cs * 128 * AW;
        const __half2* Dc = Bd + cs * 16 * BW;
#pragma unroll
        for (int ks = 0; ks < 2; ks++) {
            unsigned abase = (unsigned)__cvta_generic_to_shared(
                &Ac[lrow * AW + ks * 16 + lchunk]);
            unsigned a[4][4];
#pragma unroll
            for (int mi = 0; mi < 4; mi++)
                ldsm4(a[mi], abase + (unsigned)(mi * 16 * AW * 2));
#pragma unroll
            for (int ni = 0; ni < 4; ni++) {
                int nc = wn + ni * 8 + gid;
                unsigned b0 = *(const unsigned*)&Dc[(ks * 8 + tig    ) * BW + nc];
                unsigned b1 = *(const unsigned*)&Dc[(ks * 8 + tig + 4) * BW + nc];
#pragma unroll
                for (int mi = 0; mi < 4; mi++) {
                    mma_f16(c[mi][ni], a[mi], b0, b1);
                }
            }
        }
    }

    // epilogue: write contribution rows (plain stores, no atomics)
#pragma unroll
    for (int mi = 0; mi < 4; mi++) {
#pragma unroll
        for (int half = 0; half < 2; half++) {
            int lm = wm + mi * 16 + gid + half * 8;
            int m  = m0 + lm;
            if (m >= cnt) continue;
            int v = stok[lm];
            int tok = v & 4095, which = v >> 12;
            float* crow = &g_c[which][(size_t)tok * DIM + n0];
#pragma unroll
            for (int ni = 0; ni < 4; ni++) {
                int col = wn + ni * 8 + 2 * tig;
                float2 o;
                o.x = c[mi][ni][half * 2 + 0];
                o.y = c[mi][ni][half * 2 + 1];
                *(float2*)(crow + col) = o;
            }
        }
    }
}

// ---------------------------------------------------------------------------
// combine: out[t] = contrib[0][t] + contrib[1][t]  (fixed order, deterministic)
// Also resets g_cnt for the NEXT replay (runs after all g_cnt readers).
// ---------------------------------------------------------------------------
__global__ void combine_kernel(float* __restrict__ out) {
    if (blockIdx.x == 0 && threadIdx.x < NEXP) g_cnt[threadIdx.x] = 0;
    size_t i = ((size_t)blockIdx.x * blockDim.x + threadIdx.x) * 4;
    float4 a = *(const float4*)&g_c[0][i];
    float4 b = *(const float4*)&g_c[1][i];
    float4 o;
    o.x = a.x + b.x; o.y = a.y + b.y; o.z = a.z + b.z; o.w = a.w + b.w;
    *(float4*)(out + i) = o;
}

// ---------------------------------------------------------------------------
extern "C" void kernel_launch(void* const* d_in, const int* in_sizes, int n_in,
                              void* d_out, int out_size) {
    const float* x  = (const float*)d_in[0];   // [T, D]
    const float* gw = (const float*)d_in[1];   // [E, D]
    const float* wg = (const float*)d_in[2];   // [E, D, F]
    const float* wu = (const float*)d_in[3];   // [E, D, F]
    const float* wd = (const float*)d_in[4];   // [E, F, D]
    float* out = (float*)d_out;

    cudaFuncSetAttribute(gateup_mma, cudaFuncAttributeMaxDynamicSharedMemorySize, GU_SMEM);
    cudaFuncSetAttribute(down_mma,   cudaFuncAttributeMaxDynamicSharedMemorySize, DN_SMEM);

    prep_router<<<PR_BLOCKS, 256>>>(x, gw, wg, wu, wd);

    dim3 g2(FDIM / 128, T_TOK / 128, NEXP);   // (11, 16, 8)
    gateup_mma<<<g2, 512, GU_SMEM>>>();

    dim3 g3(DIM / 128, T_TOK / 128, NEXP);    // (16, 16, 8)
    down_mma<<<g3, 256, DN_SMEM>>>();

    combine_kernel<<<(T_TOK * DIM) / (256 * 4), 256>>>(out);
}